// round 9
// baseline (speedup 1.0000x reference)
#include <cuda_runtime.h>
#include <cstdint>

#define EMBED   1024
#define HEADS   16
#define HDIM    64
#define BATCH   2
#define SEQ     2048
#define MTOT    (BATCH*SEQ)   // 4096

// Scratch (static __device__ -- no dynamic allocation allowed)
__device__ float g_qkv [(size_t)MTOT * 3 * EMBED];   // [4096, 3072]
__device__ float g_attn[(size_t)MTOT * EMBED];       // [4096, 1024]

// ============================================================================
// helpers
// ============================================================================
__device__ __forceinline__ uint32_t smem_u32(const void* p) {
    uint32_t a;
    asm("{ .reg .u64 t; cvta.to.shared.u64 t, %1; cvt.u32.u64 %0, t; }"
        : "=r"(a) : "l"(p));
    return a;
}
__device__ __forceinline__ float f2tf32(float x) {
    uint32_t u;
    asm("cvt.rna.tf32.f32 %0, %1;" : "=r"(u) : "f"(x));
    return __uint_as_float(u);
}
__device__ __forceinline__ void ldsm_x4(uint32_t* r, uint32_t addr) {
    asm volatile("ldmatrix.sync.aligned.m8n8.x4.shared.b16 {%0,%1,%2,%3}, [%4];"
        : "=r"(r[0]), "=r"(r[1]), "=r"(r[2]), "=r"(r[3]) : "r"(addr));
}
__device__ __forceinline__ void ldsm_x2(uint32_t* r, uint32_t addr) {
    asm volatile("ldmatrix.sync.aligned.m8n8.x2.shared.b16 {%0,%1}, [%2];"
        : "=r"(r[0]), "=r"(r[1]) : "r"(addr));
}
__device__ __forceinline__ void mma_tf32(float* d, const uint32_t* a, const uint32_t* b) {
    asm volatile(
        "mma.sync.aligned.m16n8k8.row.col.f32.tf32.tf32.f32 "
        "{%0,%1,%2,%3}, {%4,%5,%6,%7}, {%8,%9}, {%0,%1,%2,%3};"
        : "+f"(d[0]), "+f"(d[1]), "+f"(d[2]), "+f"(d[3])
        : "r"(a[0]), "r"(a[1]), "r"(a[2]), "r"(a[3]), "r"(b[0]), "r"(b[1]));
}

// ============================================================================
// tf32 tensor-core GEMM (NT): C[M,N] = A[M,K] @ B[N,K]^T + bias[N]
// Round-5 version (measured 253us): 2-stage pipeline, x2 B-fragment loads.
// ============================================================================
#define BKF 32
#define G_STAGE 32768
#define GEMM_DSMEM (2 * G_STAGE + 1024)

__global__ __launch_bounds__(256, 1)
void gemm_tf32_mma(const float* __restrict__ A,
                   const float* __restrict__ B,
                   const float* __restrict__ bias,
                   float* __restrict__ C,
                   int M, int N, int K)
{
    extern __shared__ char gsm[];
    const uint32_t raw  = smem_u32(gsm);
    const uint32_t base = (raw + 1023u) & ~1023u;
    char* pb = gsm + (base - raw);

    const int tid  = threadIdx.x;
    const int wid  = tid >> 5;
    const int lane = tid & 31;
    const int m0   = blockIdx.y * 128;
    const int n0   = blockIdx.x * 128;
    const int wm   = (wid & 1) * 64;
    const int wn   = (wid >> 1) * 32;

    const int lrow  = tid >> 1;
    const int lhalf = tid & 1;
    const float* Arow = A + (size_t)(m0 + lrow) * K + lhalf * 16;
    const float* Brow = B + (size_t)(n0 + lrow) * K + lhalf * 16;
    uint32_t st_off[4];
#pragma unroll
    for (int q = 0; q < 4; q++) {
        uint32_t bo = (uint32_t)lrow * 128u + (uint32_t)lhalf * 64u + q * 16u;
        st_off[q] = bo ^ ((bo >> 3) & 0x70);
    }

    const int aseg  = lane >> 3;
    const int arow  = wm + ((aseg & 1) << 3) + (lane & 7);
    const uint32_t akb = (uint32_t)((aseg >> 1) << 4);
    const int bseg  = (lane >> 3) & 1;
    const int brow  = wn + (lane & 7);
    const uint32_t bkb = (uint32_t)(bseg << 4);
    const uint32_t swmask = (uint32_t)((lane & 7) << 4);
    const uint32_t aRowByte = (uint32_t)arow * 128u;
    const uint32_t bRowByte = (uint32_t)brow * 128u;

    float acc[4][4][4];
#pragma unroll
    for (int i = 0; i < 4; i++)
#pragma unroll
        for (int j = 0; j < 4; j++)
#pragma unroll
            for (int r = 0; r < 4; r++) acc[i][j][r] = 0.f;

    const int KCH = K / BKF;
    float4 av[4], bv[4];

#pragma unroll
    for (int q = 0; q < 4; q++) {
        av[q] = *(const float4*)(Arow + q * 4);
        bv[q] = *(const float4*)(Brow + q * 4);
    }
#pragma unroll
    for (int q = 0; q < 4; q++) {
        float4 t;
        t.x = f2tf32(av[q].x); t.y = f2tf32(av[q].y);
        t.z = f2tf32(av[q].z); t.w = f2tf32(av[q].w);
        *(float4*)(pb + st_off[q]) = t;
        t.x = f2tf32(bv[q].x); t.y = f2tf32(bv[q].y);
        t.z = f2tf32(bv[q].z); t.w = f2tf32(bv[q].w);
        *(float4*)(pb + 16384 + st_off[q]) = t;
    }

    for (int kt = 0; kt < KCH; kt++) {
        __syncthreads();

        if (kt + 1 < KCH) {
            const float* a = Arow + (size_t)(kt + 1) * BKF;
            const float* b = Brow + (size_t)(kt + 1) * BKF;
#pragma unroll
            for (int q = 0; q < 4; q++) {
                av[q] = *(const float4*)(a + q * 4);
                bv[q] = *(const float4*)(b + q * 4);
            }
        }

        const uint32_t sAa = base + (uint32_t)(kt & 1) * G_STAGE;
        const uint32_t sBa = sAa + 16384u;
#pragma unroll
        for (int ks = 0; ks < 4; ks++) {
            const uint32_t kcolA = ((uint32_t)(ks * 32) + akb) ^ swmask;
            const uint32_t kcolB = ((uint32_t)(ks * 32) + bkb) ^ swmask;
            uint32_t afr[4][4], bfr[4][2];
#pragma unroll
            for (int mt = 0; mt < 4; mt++)
                ldsm_x4(afr[mt], sAa + aRowByte + (uint32_t)(mt * 16 * 128) + kcolA);
#pragma unroll
            for (int nt = 0; nt < 4; nt++)
                ldsm_x2(bfr[nt], sBa + bRowByte + (uint32_t)(nt * 8 * 128) + kcolB);
#pragma unroll
            for (int mt = 0; mt < 4; mt++)
#pragma unroll
                for (int nt = 0; nt < 4; nt++)
                    mma_tf32(acc[mt][nt], afr[mt], bfr[nt]);
        }

        if (kt + 1 < KCH) {
            char* dst = pb + ((kt + 1) & 1) * G_STAGE;
#pragma unroll
            for (int q = 0; q < 4; q++) {
                float4 t;
                t.x = f2tf32(av[q].x); t.y = f2tf32(av[q].y);
                t.z = f2tf32(av[q].z); t.w = f2tf32(av[q].w);
                *(float4*)(dst + st_off[q]) = t;
                t.x = f2tf32(bv[q].x); t.y = f2tf32(bv[q].y);
                t.z = f2tf32(bv[q].z); t.w = f2tf32(bv[q].w);
                *(float4*)(dst + 16384 + st_off[q]) = t;
            }
        }
    }

    const int rbase = m0 + wm + (lane >> 2);
    const int cbase = n0 + wn + (lane & 3) * 2;
#pragma unroll
    for (int mt = 0; mt < 4; mt++) {
        const int r0 = rbase + mt * 16;
#pragma unroll
        for (int nt = 0; nt < 4; nt++) {
            const int c = cbase + nt * 8;
            const float b0 = __ldg(bias + c);
            const float b1 = __ldg(bias + c + 1);
            float2 v0, v1;
            v0.x = acc[mt][nt][0] + b0; v0.y = acc[mt][nt][1] + b1;
            v1.x = acc[mt][nt][2] + b0; v1.y = acc[mt][nt][3] + b1;
            *(float2*)&C[(size_t)r0 * N + c]       = v0;
            *(float2*)&C[(size_t)(r0 + 8) * N + c] = v1;
        }
    }
}

// ============================================================================
// Tensor-core flash attention (tf32 mma).
// NEW: BQ=128 with 128 threads / 4 warps; each warp owns 32 q-rows
// (2 m-fragments). Halves cross-warp K/V fragment re-reads (L1-bound fix)
// and fits 2 CTAs/SM (independent CTAs overlap softmax with mma).
// x2 B-fragment loads (conflict-free, proven).
// ============================================================================
#define BQ  128
#define BKV 64

// smem layout (bytes from 1024-aligned base):
//  sQ  [128][64]f : 0      .. 32768
//  sK  [ 64][64]f : 32768  .. 49152
//  sVT [ 64][64]f : 49152  .. 65536
//  sP  [128][64]f : 65536  .. 98304
//  sM  [64]i      : 98304  .. 98560
#define FA_SMEM (98560 + 1024)

__device__ __forceinline__ uint32_t sw256(int row, int chunk) {
    return (uint32_t)row * 256u + (uint32_t)((chunk ^ (row & 7)) << 4);
}

__global__ __launch_bounds__(128, 2)
void flash_attn_tc(const float* __restrict__ qkv,
                   const int*   __restrict__ mask,
                   float*       __restrict__ out)
{
    extern __shared__ char fsm[];
    const uint32_t raw  = smem_u32(fsm);
    const uint32_t base = (raw + 1023u) & ~1023u;
    char* pb = fsm + (base - raw);
    char* sQ  = pb;
    char* sK  = pb + 32768;
    char* sVT = pb + 49152;
    char* sP  = pb + 65536;
    int*  sM  = (int*)(pb + 98304);
    const uint32_t aQ  = base;
    const uint32_t aK  = base + 32768;
    const uint32_t aVT = base + 49152;
    const uint32_t aP  = base + 65536;

    const int tid  = threadIdx.x;
    const int wid  = tid >> 5;       // 0..3
    const int lane = tid & 31;
    const int qb   = blockIdx.x;
    const int h    = blockIdx.y;
    const int b    = blockIdx.z;

    const size_t rs = 3 * EMBED;
    const float* qg = qkv + (size_t)(b * SEQ) * rs + h * HDIM;
    const float* kg = qg + EMBED;
    const float* vg = qg + 2 * EMBED;
    const int*   mg = mask + b * SEQ;

    // ---- load Q tile [128][64]: one row per thread, 16 chunks
    {
        const float* src = qg + (size_t)(qb * BQ + tid) * rs;
#pragma unroll
        for (int c = 0; c < 16; c++) {
            float4 v = *(const float4*)(src + c * 4);
            v.x = f2tf32(v.x); v.y = f2tf32(v.y);
            v.z = f2tf32(v.z); v.w = f2tf32(v.w);
            *(float4*)(sQ + sw256(tid, c)) = v;
        }
    }
    __syncthreads();

    // ---- hoist Q fragments: 2 m-tiles x 8 k-steps
    const int arow0 = wid * 32 + ((lane >> 3) & 1) * 8 + (lane & 7);
    const int ach   = lane >> 4;
    uint32_t qf[2][8][4];
#pragma unroll
    for (int mt = 0; mt < 2; mt++)
#pragma unroll
        for (int ks = 0; ks < 8; ks++)
            ldsm_x4(qf[mt][ks], aQ + sw256(arow0 + mt * 16, ks * 2 + ach));

    const int bln = lane & 7;
    const int bch = (lane >> 3) & 1;

    float m_i[2][2], l_i[2][2];
#pragma unroll
    for (int mt = 0; mt < 2; mt++) {
        m_i[mt][0] = -1e30f; m_i[mt][1] = -1e30f;
        l_i[mt][0] = 0.f;    l_i[mt][1] = 0.f;
    }
    float oacc[2][8][4];
#pragma unroll
    for (int mt = 0; mt < 2; mt++)
#pragma unroll
        for (int j = 0; j < 8; j++)
#pragma unroll
            for (int r = 0; r < 4; r++) oacc[mt][j][r] = 0.f;

    for (int kt = 0; kt < SEQ / BKV; kt++) {
        __syncthreads();   // prev PV mma done reading sK/sVT/sP

        // ---- load K tile [64 keys][64 d]: row = tid>>1, 8 chunks
        {
            const int r  = tid >> 1;
            const int cb = (tid & 1) * 8;
            const float* src = kg + (size_t)(kt * BKV + r) * rs;
#pragma unroll
            for (int q = 0; q < 8; q++) {
                const int c = cb + q;
                float4 v = *(const float4*)(src + c * 4);
                v.x = f2tf32(v.x); v.y = f2tf32(v.y);
                v.z = f2tf32(v.z); v.w = f2tf32(v.w);
                *(float4*)(sK + sw256(r, c)) = v;
            }
        }
        // ---- load V tile transposed -> sVT[d][key]: key = tid>>1, 32 d
        {
            const int key = tid >> 1;
            const int db  = (tid & 1) * 32;
            const float* src = vg + (size_t)(kt * BKV + key) * rs + db;
            const int kc = key >> 2;
            const int kb = (key & 3) * 4;
#pragma unroll
            for (int q = 0; q < 8; q++) {
                float4 v = *(const float4*)(src + q * 4);
                const int d0 = db + q * 4;
                *(float*)(sVT + sw256(d0 + 0, kc) + kb) = f2tf32(v.x);
                *(float*)(sVT + sw256(d0 + 1, kc) + kb) = f2tf32(v.y);
                *(float*)(sVT + sw256(d0 + 2, kc) + kb) = f2tf32(v.z);
                *(float*)(sVT + sw256(d0 + 3, kc) + kb) = f2tf32(v.w);
            }
        }
        if (tid < BKV) sM[tid] = mg[kt * BKV + tid];
        __syncthreads();

        // ---- S = Q K^T : per warp 32 x 64; B-frag loaded once, used by both mt
        float sacc[2][8][4];
#pragma unroll
        for (int mt = 0; mt < 2; mt++)
#pragma unroll
            for (int j = 0; j < 8; j++)
#pragma unroll
                for (int r = 0; r < 4; r++) sacc[mt][j][r] = 0.f;
#pragma unroll
        for (int ks = 0; ks < 8; ks++) {
            uint32_t bfr[8][2];
#pragma unroll
            for (int nf = 0; nf < 8; nf++)
                ldsm_x2(bfr[nf], aK + sw256(nf * 8 + bln, ks * 2 + bch));
#pragma unroll
            for (int mt = 0; mt < 2; mt++)
#pragma unroll
                for (int nf = 0; nf < 8; nf++)
                    mma_tf32(sacc[mt][nf], qf[mt][ks], bfr[nf]);
        }

        // ---- fragment softmax + P store, per m-tile
#pragma unroll
        for (int mt = 0; mt < 2; mt++) {
            float rmax0 = -1e30f, rmax1 = -1e30f;
#pragma unroll
            for (int j = 0; j < 8; j++) {
                const int c = j * 8 + (lane & 3) * 2;
                const int mk0 = sM[c], mk1 = sM[c + 1];
                sacc[mt][j][0] = mk0 ? sacc[mt][j][0] * 0.125f : -1e30f;
                sacc[mt][j][1] = mk1 ? sacc[mt][j][1] * 0.125f : -1e30f;
                sacc[mt][j][2] = mk0 ? sacc[mt][j][2] * 0.125f : -1e30f;
                sacc[mt][j][3] = mk1 ? sacc[mt][j][3] * 0.125f : -1e30f;
                rmax0 = fmaxf(rmax0, fmaxf(sacc[mt][j][0], sacc[mt][j][1]));
                rmax1 = fmaxf(rmax1, fmaxf(sacc[mt][j][2], sacc[mt][j][3]));
            }
            rmax0 = fmaxf(rmax0, __shfl_xor_sync(0xffffffffu, rmax0, 1));
            rmax0 = fmaxf(rmax0, __shfl_xor_sync(0xffffffffu, rmax0, 2));
            rmax1 = fmaxf(rmax1, __shfl_xor_sync(0xffffffffu, rmax1, 1));
            rmax1 = fmaxf(rmax1, __shfl_xor_sync(0xffffffffu, rmax1, 2));

            const float mn0 = fmaxf(m_i[mt][0], rmax0);
            const float mn1 = fmaxf(m_i[mt][1], rmax1);
            const float cr0 = __expf(m_i[mt][0] - mn0);
            const float cr1 = __expf(m_i[mt][1] - mn1);
            m_i[mt][0] = mn0; m_i[mt][1] = mn1;

            float rsum0 = 0.f, rsum1 = 0.f;
#pragma unroll
            for (int j = 0; j < 8; j++) {
                sacc[mt][j][0] = __expf(sacc[mt][j][0] - mn0);
                sacc[mt][j][1] = __expf(sacc[mt][j][1] - mn0);
                sacc[mt][j][2] = __expf(sacc[mt][j][2] - mn1);
                sacc[mt][j][3] = __expf(sacc[mt][j][3] - mn1);
                rsum0 += sacc[mt][j][0] + sacc[mt][j][1];
                rsum1 += sacc[mt][j][2] + sacc[mt][j][3];
            }
            rsum0 += __shfl_xor_sync(0xffffffffu, rsum0, 1);
            rsum0 += __shfl_xor_sync(0xffffffffu, rsum0, 2);
            rsum1 += __shfl_xor_sync(0xffffffffu, rsum1, 1);
            rsum1 += __shfl_xor_sync(0xffffffffu, rsum1, 2);
            l_i[mt][0] = l_i[mt][0] * cr0 + rsum0;
            l_i[mt][1] = l_i[mt][1] * cr1 + rsum1;

#pragma unroll
            for (int j = 0; j < 8; j++) {
                oacc[mt][j][0] *= cr0; oacc[mt][j][1] *= cr0;
                oacc[mt][j][2] *= cr1; oacc[mt][j][3] *= cr1;
            }

            const int r0 = wid * 32 + mt * 16 + (lane >> 2);
#pragma unroll
            for (int j = 0; j < 8; j++) {
                const int c = j * 8 + (lane & 3) * 2;
                const int ch = c >> 2;
                const int cb = (c & 3) * 4;
                float2 v0, v1;
                v0.x = f2tf32(sacc[mt][j][0]); v0.y = f2tf32(sacc[mt][j][1]);
                v1.x = f2tf32(sacc[mt][j][2]); v1.y = f2tf32(sacc[mt][j][3]);
                *(float2*)(sP + sw256(r0,     ch) + cb) = v0;
                *(float2*)(sP + sw256(r0 + 8, ch) + cb) = v1;
            }
        }
        __syncwarp();

        // ---- O += P V^T : B-frag loaded once per ks, used by both mt
#pragma unroll
        for (int ks = 0; ks < 8; ks++) {
            uint32_t af[2][4];
#pragma unroll
            for (int mt = 0; mt < 2; mt++)
                ldsm_x4(af[mt], aP + sw256(arow0 + mt * 16, ks * 2 + ach));
            uint32_t bfr[8][2];
#pragma unroll
            for (int nf = 0; nf < 8; nf++)
                ldsm_x2(bfr[nf], aVT + sw256(nf * 8 + bln, ks * 2 + bch));
#pragma unroll
            for (int mt = 0; mt < 2; mt++)
#pragma unroll
                for (int nf = 0; nf < 8; nf++)
                    mma_tf32(oacc[mt][nf], af[mt], bfr[nf]);
        }
    }

    // ---- epilogue: normalize, write to [b, s, h*64 + d]
#pragma unroll
    for (int mt = 0; mt < 2; mt++) {
        const float inv0 = 1.0f / l_i[mt][0];
        const float inv1 = 1.0f / l_i[mt][1];
        const int r0 = qb * BQ + wid * 32 + mt * 16 + (lane >> 2);
        const int c0 = h * HDIM + (lane & 3) * 2;
#pragma unroll
        for (int j = 0; j < 8; j++) {
            const int c = c0 + j * 8;
            float2 v0, v1;
            v0.x = oacc[mt][j][0] * inv0; v0.y = oacc[mt][j][1] * inv0;
            v1.x = oacc[mt][j][2] * inv1; v1.y = oacc[mt][j][3] * inv1;
            *(float2*)&out[(size_t)(b * SEQ + r0)     * EMBED + c] = v0;
            *(float2*)&out[(size_t)(b * SEQ + r0 + 8) * EMBED + c] = v1;
        }
    }
}

// ---------------------------------------------------------------------------
extern "C" void kernel_launch(void* const* d_in, const int* in_sizes, int n_in,
                              void* d_out, int out_size)
{
    const float* x    = (const float*)d_in[0];
    const int*   mask = (const int*)  d_in[1];
    const float* Wqkv = (const float*)d_in[2];
    const float* bqkv = (const float*)d_in[3];
    const float* Wout = (const float*)d_in[4];
    const float* bout = (const float*)d_in[5];
    float* out = (float*)d_out;

    float *qkv = nullptr, *attn = nullptr;
    cudaGetSymbolAddress((void**)&qkv,  g_qkv);
    cudaGetSymbolAddress((void**)&attn, g_attn);

    cudaFuncSetAttribute(gemm_tf32_mma,
                         cudaFuncAttributeMaxDynamicSharedMemorySize, GEMM_DSMEM);
    cudaFuncSetAttribute(flash_attn_tc,
                         cudaFuncAttributeMaxDynamicSharedMemorySize, FA_SMEM);

    // 1) qkv = x @ Wqkv^T + bqkv       [4096, 3072]
    {
        dim3 grid((3 * EMBED) / 128, MTOT / 128);
        gemm_tf32_mma<<<grid, 256, GEMM_DSMEM>>>(x, Wqkv, bqkv, qkv,
                                                 MTOT, 3 * EMBED, EMBED);
    }
    // 2) flash attention -> attn       [4096, 1024]
    {
        dim3 grid(SEQ / BQ, HEADS, BATCH);
        flash_attn_tc<<<grid, 128, FA_SMEM>>>(qkv, mask, attn);
    }
    // 3) out = attn @ Wout^T + bout    [4096, 1024]
    {
        dim3 grid(EMBED / 128, MTOT / 128);
        gemm_tf32_mma<<<grid, 256, GEMM_DSMEM>>>(attn, Wout, bout, out,
                                                 MTOT, EMBED, EMBED);
    }
}

// round 10
// speedup vs baseline: 1.3050x; 1.3050x over previous
#include <cuda_runtime.h>
#include <cstdint>

#define EMBED   1024
#define HEADS   16
#define HDIM    64
#define BATCH   2
#define SEQ     2048
#define MTOT    (BATCH*SEQ)   // 4096

// Scratch (static __device__ -- no dynamic allocation allowed)
__device__ float g_qkv [(size_t)MTOT * 3 * EMBED];   // [4096, 3072]
__device__ float g_attn[(size_t)MTOT * EMBED];       // [4096, 1024]

// ============================================================================
// helpers
// ============================================================================
__device__ __forceinline__ uint32_t smem_u32(const void* p) {
    uint32_t a;
    asm("{ .reg .u64 t; cvta.to.shared.u64 t, %1; cvt.u32.u64 %0, t; }"
        : "=r"(a) : "l"(p));
    return a;
}
__device__ __forceinline__ float f2tf32(float x) {
    uint32_t u;
    asm("cvt.rna.tf32.f32 %0, %1;" : "=r"(u) : "f"(x));
    return __uint_as_float(u);
}
__device__ __forceinline__ void ldsm_x4(uint32_t* r, uint32_t addr) {
    asm volatile("ldmatrix.sync.aligned.m8n8.x4.shared.b16 {%0,%1,%2,%3}, [%4];"
        : "=r"(r[0]), "=r"(r[1]), "=r"(r[2]), "=r"(r[3]) : "r"(addr));
}
__device__ __forceinline__ void ldsm_x2(uint32_t* r, uint32_t addr) {
    asm volatile("ldmatrix.sync.aligned.m8n8.x2.shared.b16 {%0,%1}, [%2];"
        : "=r"(r[0]), "=r"(r[1]) : "r"(addr));
}
__device__ __forceinline__ void mma_tf32(float* d, const uint32_t* a, const uint32_t* b) {
    asm volatile(
        "mma.sync.aligned.m16n8k8.row.col.f32.tf32.tf32.f32 "
        "{%0,%1,%2,%3}, {%4,%5,%6,%7}, {%8,%9}, {%0,%1,%2,%3};"
        : "+f"(d[0]), "+f"(d[1]), "+f"(d[2]), "+f"(d[3])
        : "r"(a[0]), "r"(a[1]), "r"(a[2]), "r"(a[3]), "r"(b[0]), "r"(b[1]));
}

// ============================================================================
// tf32 tensor-core GEMM (NT): C[M,N] = A[M,K] @ B[N,K]^T + bias[N]
// NEW shape: CTA tile 128(M) x 64(N), 128 threads (4 warps in 2x2, warp tile
// 64x32 -- identical per-warp code to the proven version). 2-stage pipeline.
// ~50 KB smem, ~175 regs -> 2 CTAs/SM: independent CTAs overlap each other's
// load/convert/barrier phases with mma (the measured 33%-tensor stall fix).
// ============================================================================
#define BKF 32
#define GA_BYTES 16384                    // A stage: 128 rows x 128B
#define GB_BYTES 8192                     // B stage:  64 rows x 128B
#define G_STAGE  (GA_BYTES + GB_BYTES)    // 24576
#define GEMM_DSMEM (2 * G_STAGE + 1024)   // 50176

__global__ __launch_bounds__(128, 2)
void gemm_tf32_mma(const float* __restrict__ A,
                   const float* __restrict__ B,
                   const float* __restrict__ bias,
                   float* __restrict__ C,
                   int M, int N, int K)
{
    extern __shared__ char gsm[];
    const uint32_t raw  = smem_u32(gsm);
    const uint32_t base = (raw + 1023u) & ~1023u;
    char* pb = gsm + (base - raw);

    const int tid  = threadIdx.x;
    const int wid  = tid >> 5;          // 0..3
    const int lane = tid & 31;
    const int m0   = blockIdx.y * 128;
    const int n0   = blockIdx.x * 64;
    const int wm   = (wid & 1) * 64;    // warp m offset
    const int wn   = (wid >> 1) * 32;   // warp n offset (0 or 32)

    // ---- loader mapping
    // A: one full 32-float row per thread (8 chunks)
    const float* Arow = A + (size_t)(m0 + tid) * K;
    uint32_t stA[8];
#pragma unroll
    for (int q = 0; q < 8; q++) {
        uint32_t bo = (uint32_t)tid * 128u + q * 16u;
        stA[q] = bo ^ ((bo >> 3) & 0x70);
    }
    // B: row = tid>>1, half = tid&1 (16 floats = 4 chunks)
    const float* Brow = B + (size_t)(n0 + (tid >> 1)) * K + (tid & 1) * 16;
    uint32_t stB[4];
#pragma unroll
    for (int q = 0; q < 4; q++) {
        uint32_t bo = (uint32_t)(tid >> 1) * 128u + (uint32_t)(tid & 1) * 64u + q * 16u;
        stB[q] = bo ^ ((bo >> 3) & 0x70);
    }

    // ---- ldmatrix addressing (identical per-warp pattern to proven version)
    const int aseg  = lane >> 3;
    const int arow  = wm + ((aseg & 1) << 3) + (lane & 7);
    const uint32_t akb = (uint32_t)((aseg >> 1) << 4);
    const int bseg  = (lane >> 3) & 1;
    const int brow  = wn + (lane & 7);
    const uint32_t bkb = (uint32_t)(bseg << 4);
    const uint32_t swmask = (uint32_t)((lane & 7) << 4);
    const uint32_t aRowByte = (uint32_t)arow * 128u;
    const uint32_t bRowByte = (uint32_t)brow * 128u;

    float acc[4][4][4];
#pragma unroll
    for (int i = 0; i < 4; i++)
#pragma unroll
        for (int j = 0; j < 4; j++)
#pragma unroll
            for (int r = 0; r < 4; r++) acc[i][j][r] = 0.f;

    const int KCH = K / BKF;
    float4 av[8], bv[4];

    // prologue: tile 0 -> stage 0
#pragma unroll
    for (int q = 0; q < 8; q++) av[q] = *(const float4*)(Arow + q * 4);
#pragma unroll
    for (int q = 0; q < 4; q++) bv[q] = *(const float4*)(Brow + q * 4);
#pragma unroll
    for (int q = 0; q < 8; q++) {
        float4 t;
        t.x = f2tf32(av[q].x); t.y = f2tf32(av[q].y);
        t.z = f2tf32(av[q].z); t.w = f2tf32(av[q].w);
        *(float4*)(pb + stA[q]) = t;
    }
#pragma unroll
    for (int q = 0; q < 4; q++) {
        float4 t;
        t.x = f2tf32(bv[q].x); t.y = f2tf32(bv[q].y);
        t.z = f2tf32(bv[q].z); t.w = f2tf32(bv[q].w);
        *(float4*)(pb + GA_BYTES + stB[q]) = t;
    }

    for (int kt = 0; kt < KCH; kt++) {
        __syncthreads();   // stage[kt&1] visible; stage[(kt+1)&1] free

        if (kt + 1 < KCH) {
            const float* a = Arow + (size_t)(kt + 1) * BKF;
            const float* b = Brow + (size_t)(kt + 1) * BKF;
#pragma unroll
            for (int q = 0; q < 8; q++) av[q] = *(const float4*)(a + q * 4);
#pragma unroll
            for (int q = 0; q < 4; q++) bv[q] = *(const float4*)(b + q * 4);
        }

        const uint32_t sAa = base + (uint32_t)(kt & 1) * G_STAGE;
        const uint32_t sBa = sAa + GA_BYTES;
#pragma unroll
        for (int ks = 0; ks < 4; ks++) {
            const uint32_t kcolA = ((uint32_t)(ks * 32) + akb) ^ swmask;
            const uint32_t kcolB = ((uint32_t)(ks * 32) + bkb) ^ swmask;
            uint32_t afr[4][4], bfr[4][2];
#pragma unroll
            for (int mt = 0; mt < 4; mt++)
                ldsm_x4(afr[mt], sAa + aRowByte + (uint32_t)(mt * 16 * 128) + kcolA);
#pragma unroll
            for (int nt = 0; nt < 4; nt++)
                ldsm_x2(bfr[nt], sBa + bRowByte + (uint32_t)(nt * 8 * 128) + kcolB);
#pragma unroll
            for (int mt = 0; mt < 4; mt++)
#pragma unroll
                for (int nt = 0; nt < 4; nt++)
                    mma_tf32(acc[mt][nt], afr[mt], bfr[nt]);
        }

        if (kt + 1 < KCH) {
            char* dst = pb + ((kt + 1) & 1) * G_STAGE;
#pragma unroll
            for (int q = 0; q < 8; q++) {
                float4 t;
                t.x = f2tf32(av[q].x); t.y = f2tf32(av[q].y);
                t.z = f2tf32(av[q].z); t.w = f2tf32(av[q].w);
                *(float4*)(dst + stA[q]) = t;
            }
#pragma unroll
            for (int q = 0; q < 4; q++) {
                float4 t;
                t.x = f2tf32(bv[q].x); t.y = f2tf32(bv[q].y);
                t.z = f2tf32(bv[q].z); t.w = f2tf32(bv[q].w);
                *(float4*)(dst + GA_BYTES + stB[q]) = t;
            }
        }
    }

    const int rbase = m0 + wm + (lane >> 2);
    const int cbase = n0 + wn + (lane & 3) * 2;
#pragma unroll
    for (int mt = 0; mt < 4; mt++) {
        const int r0 = rbase + mt * 16;
#pragma unroll
        for (int nt = 0; nt < 4; nt++) {
            const int c = cbase + nt * 8;
            const float b0 = __ldg(bias + c);
            const float b1 = __ldg(bias + c + 1);
            float2 v0, v1;
            v0.x = acc[mt][nt][0] + b0; v0.y = acc[mt][nt][1] + b1;
            v1.x = acc[mt][nt][2] + b0; v1.y = acc[mt][nt][3] + b1;
            *(float2*)&C[(size_t)r0 * N + c]       = v0;
            *(float2*)&C[(size_t)(r0 + 8) * N + c] = v1;
        }
    }
}

// ============================================================================
// Tensor-core flash attention (tf32 mma) — ROUND-4 EXACT (best measured):
// BQ=128, 256 threads / 8 warps, 16 q-rows/warp, direct LDG, x2 B-frags.
// ============================================================================
#define BQ  128
#define BKV 64

// smem layout (bytes from 1024-aligned base):
//  sQ  [128][64]f : 0      .. 32768
//  sK  [ 64][64]f : 32768  .. 49152
//  sVT [ 64][64]f : 49152  .. 65536
//  sP  [128][64]f : 65536  .. 98304
//  sM  [64]i      : 98304  .. 98560
#define FA_SMEM (98560 + 1024)

__device__ __forceinline__ uint32_t sw256(int row, int chunk) {
    return (uint32_t)row * 256u + (uint32_t)((chunk ^ (row & 7)) << 4);
}

__global__ __launch_bounds__(256, 1)
void flash_attn_tc(const float* __restrict__ qkv,
                   const int*   __restrict__ mask,
                   float*       __restrict__ out)
{
    extern __shared__ char fsm[];
    const uint32_t raw  = smem_u32(fsm);
    const uint32_t base = (raw + 1023u) & ~1023u;
    char* pb = fsm + (base - raw);
    char* sQ  = pb;
    char* sK  = pb + 32768;
    char* sVT = pb + 49152;
    char* sP  = pb + 65536;
    int*  sM  = (int*)(pb + 98304);
    const uint32_t aQ  = base;
    const uint32_t aK  = base + 32768;
    const uint32_t aVT = base + 49152;
    const uint32_t aP  = base + 65536;

    const int tid  = threadIdx.x;
    const int wid  = tid >> 5;
    const int lane = tid & 31;
    const int qb   = blockIdx.x;
    const int h    = blockIdx.y;
    const int b    = blockIdx.z;

    const size_t rs = 3 * EMBED;
    const float* qg = qkv + (size_t)(b * SEQ) * rs + h * HDIM;
    const float* kg = qg + EMBED;
    const float* vg = qg + 2 * EMBED;
    const int*   mg = mask + b * SEQ;

    // ---- load Q tile [128][64]
    {
        const int r  = tid >> 1;
        const int cb = (tid & 1) * 8;
        const float* src = qg + (size_t)(qb * BQ + r) * rs;
#pragma unroll
        for (int q = 0; q < 8; q++) {
            const int c = cb + q;
            float4 v = *(const float4*)(src + c * 4);
            v.x = f2tf32(v.x); v.y = f2tf32(v.y);
            v.z = f2tf32(v.z); v.w = f2tf32(v.w);
            *(float4*)(sQ + sw256(r, c)) = v;
        }
    }
    __syncthreads();

    // ---- hoist Q fragments for all 8 k-steps
    const int arow = wid * 16 + ((lane >> 3) & 1) * 8 + (lane & 7);
    const int ach  = lane >> 4;
    uint32_t qf[8][4];
#pragma unroll
    for (int ks = 0; ks < 8; ks++)
        ldsm_x4(qf[ks], aQ + sw256(arow, ks * 2 + ach));

    const int bln = lane & 7;
    const int bch = (lane >> 3) & 1;

    float m_i[2] = {-1e30f, -1e30f};
    float l_i[2] = {0.f, 0.f};
    float oacc[8][4];
#pragma unroll
    for (int j = 0; j < 8; j++)
#pragma unroll
        for (int r = 0; r < 4; r++) oacc[j][r] = 0.f;

    for (int kt = 0; kt < SEQ / BKV; kt++) {
        __syncthreads();   // prev PV mma done reading sK/sVT/sP

        // ---- load K tile [64 keys][64 d]
        {
            const int r  = tid >> 2;
            const int cb = (tid & 3) * 4;
            const float* src = kg + (size_t)(kt * BKV + r) * rs;
#pragma unroll
            for (int q = 0; q < 4; q++) {
                const int c = cb + q;
                float4 v = *(const float4*)(src + c * 4);
                v.x = f2tf32(v.x); v.y = f2tf32(v.y);
                v.z = f2tf32(v.z); v.w = f2tf32(v.w);
                *(float4*)(sK + sw256(r, c)) = v;
            }
        }
        // ---- load V tile transposed -> sVT[d][key]
        {
            const int key = tid >> 2;
            const int db  = (tid & 3) * 16;
            const float* src = vg + (size_t)(kt * BKV + key) * rs + db;
            const int kc = key >> 2;
            const int kb = (key & 3) * 4;
#pragma unroll
            for (int q = 0; q < 4; q++) {
                float4 v = *(const float4*)(src + q * 4);
                const int d0 = db + q * 4;
                *(float*)(sVT + sw256(d0 + 0, kc) + kb) = f2tf32(v.x);
                *(float*)(sVT + sw256(d0 + 1, kc) + kb) = f2tf32(v.y);
                *(float*)(sVT + sw256(d0 + 2, kc) + kb) = f2tf32(v.z);
                *(float*)(sVT + sw256(d0 + 3, kc) + kb) = f2tf32(v.w);
            }
        }
        if (tid < BKV) sM[tid] = mg[kt * BKV + tid];
        __syncthreads();

        // ---- S = Q K^T : per warp 16 x 64
        float sacc[8][4];
#pragma unroll
        for (int j = 0; j < 8; j++)
#pragma unroll
            for (int r = 0; r < 4; r++) sacc[j][r] = 0.f;
#pragma unroll
        for (int ks = 0; ks < 8; ks++) {
            uint32_t bfr[8][2];
#pragma unroll
            for (int nf = 0; nf < 8; nf++)
                ldsm_x2(bfr[nf], aK + sw256(nf * 8 + bln, ks * 2 + bch));
#pragma unroll
            for (int nf = 0; nf < 8; nf++)
                mma_tf32(sacc[nf], qf[ks], bfr[nf]);
        }

        // ---- fragment softmax
        float rmax0 = -1e30f, rmax1 = -1e30f;
#pragma unroll
        for (int j = 0; j < 8; j++) {
            const int c = j * 8 + (lane & 3) * 2;
            const int mk0 = sM[c], mk1 = sM[c + 1];
            sacc[j][0] = mk0 ? sacc[j][0] * 0.125f : -1e30f;
            sacc[j][1] = mk1 ? sacc[j][1] * 0.125f : -1e30f;
            sacc[j][2] = mk0 ? sacc[j][2] * 0.125f : -1e30f;
            sacc[j][3] = mk1 ? sacc[j][3] * 0.125f : -1e30f;
            rmax0 = fmaxf(rmax0, fmaxf(sacc[j][0], sacc[j][1]));
            rmax1 = fmaxf(rmax1, fmaxf(sacc[j][2], sacc[j][3]));
        }
        rmax0 = fmaxf(rmax0, __shfl_xor_sync(0xffffffffu, rmax0, 1));
        rmax0 = fmaxf(rmax0, __shfl_xor_sync(0xffffffffu, rmax0, 2));
        rmax1 = fmaxf(rmax1, __shfl_xor_sync(0xffffffffu, rmax1, 1));
        rmax1 = fmaxf(rmax1, __shfl_xor_sync(0xffffffffu, rmax1, 2));

        const float mn0 = fmaxf(m_i[0], rmax0);
        const float mn1 = fmaxf(m_i[1], rmax1);
        const float cr0 = __expf(m_i[0] - mn0);
        const float cr1 = __expf(m_i[1] - mn1);
        m_i[0] = mn0; m_i[1] = mn1;

        float rsum0 = 0.f, rsum1 = 0.f;
#pragma unroll
        for (int j = 0; j < 8; j++) {
            sacc[j][0] = __expf(sacc[j][0] - mn0);
            sacc[j][1] = __expf(sacc[j][1] - mn0);
            sacc[j][2] = __expf(sacc[j][2] - mn1);
            sacc[j][3] = __expf(sacc[j][3] - mn1);
            rsum0 += sacc[j][0] + sacc[j][1];
            rsum1 += sacc[j][2] + sacc[j][3];
        }
        rsum0 += __shfl_xor_sync(0xffffffffu, rsum0, 1);
        rsum0 += __shfl_xor_sync(0xffffffffu, rsum0, 2);
        rsum1 += __shfl_xor_sync(0xffffffffu, rsum1, 1);
        rsum1 += __shfl_xor_sync(0xffffffffu, rsum1, 2);
        l_i[0] = l_i[0] * cr0 + rsum0;
        l_i[1] = l_i[1] * cr1 + rsum1;

#pragma unroll
        for (int j = 0; j < 8; j++) {
            oacc[j][0] *= cr0; oacc[j][1] *= cr0;
            oacc[j][2] *= cr1; oacc[j][3] *= cr1;
        }

        // ---- store P (tf32); rows warp-local
        {
            const int r0 = wid * 16 + (lane >> 2);
#pragma unroll
            for (int j = 0; j < 8; j++) {
                const int c = j * 8 + (lane & 3) * 2;
                const int ch = c >> 2;
                const int cb = (c & 3) * 4;
                float2 v0, v1;
                v0.x = f2tf32(sacc[j][0]); v0.y = f2tf32(sacc[j][1]);
                v1.x = f2tf32(sacc[j][2]); v1.y = f2tf32(sacc[j][3]);
                *(float2*)(sP + sw256(r0,     ch) + cb) = v0;
                *(float2*)(sP + sw256(r0 + 8, ch) + cb) = v1;
            }
        }
        __syncwarp();

        // ---- O += P V^T
#pragma unroll
        for (int ks = 0; ks < 8; ks++) {
            uint32_t af[4];
            ldsm_x4(af, aP + sw256(arow, ks * 2 + ach));
            uint32_t bfr[8][2];
#pragma unroll
            for (int nf = 0; nf < 8; nf++)
                ldsm_x2(bfr[nf], aVT + sw256(nf * 8 + bln, ks * 2 + bch));
#pragma unroll
            for (int nf = 0; nf < 8; nf++)
                mma_tf32(oacc[nf], af, bfr[nf]);
        }
    }

    // ---- epilogue: normalize, write to [b, s, h*64 + d]
    const float inv0 = 1.0f / l_i[0];
    const float inv1 = 1.0f / l_i[1];
    const int r0 = qb * BQ + wid * 16 + (lane >> 2);
    const int c0 = h * HDIM + (lane & 3) * 2;
#pragma unroll
    for (int j = 0; j < 8; j++) {
        const int c = c0 + j * 8;
        float2 v0, v1;
        v0.x = oacc[j][0] * inv0; v0.y = oacc[j][1] * inv0;
        v1.x = oacc[j][2] * inv1; v1.y = oacc[j][3] * inv1;
        *(float2*)&out[(size_t)(b * SEQ + r0)     * EMBED + c] = v0;
        *(float2*)&out[(size_t)(b * SEQ + r0 + 8) * EMBED + c] = v1;
    }
}

// ---------------------------------------------------------------------------
extern "C" void kernel_launch(void* const* d_in, const int* in_sizes, int n_in,
                              void* d_out, int out_size)
{
    const float* x    = (const float*)d_in[0];
    const int*   mask = (const int*)  d_in[1];
    const float* Wqkv = (const float*)d_in[2];
    const float* bqkv = (const float*)d_in[3];
    const float* Wout = (const float*)d_in[4];
    const float* bout = (const float*)d_in[5];
    float* out = (float*)d_out;

    float *qkv = nullptr, *attn = nullptr;
    cudaGetSymbolAddress((void**)&qkv,  g_qkv);
    cudaGetSymbolAddress((void**)&attn, g_attn);

    cudaFuncSetAttribute(gemm_tf32_mma,
                         cudaFuncAttributeMaxDynamicSharedMemorySize, GEMM_DSMEM);
    cudaFuncSetAttribute(flash_attn_tc,
                         cudaFuncAttributeMaxDynamicSharedMemorySize, FA_SMEM);

    // 1) qkv = x @ Wqkv^T + bqkv       [4096, 3072]
    {
        dim3 grid((3 * EMBED) / 64, MTOT / 128);
        gemm_tf32_mma<<<grid, 128, GEMM_DSMEM>>>(x, Wqkv, bqkv, qkv,
                                                 MTOT, 3 * EMBED, EMBED);
    }
    // 2) flash attention -> attn       [4096, 1024]
    {
        dim3 grid(SEQ / BQ, HEADS, BATCH);
        flash_attn_tc<<<grid, 256, FA_SMEM>>>(qkv, mask, attn);
    }
    // 3) out = attn @ Wout^T + bout    [4096, 1024]
    {
        dim3 grid(EMBED / 64, MTOT / 128);
        gemm_tf32_mma<<<grid, 128, GEMM_DSMEM>>>(attn, Wout, bout, out,
                                                 MTOT, EMBED, EMBED);
    }
}

// round 11
// speedup vs baseline: 1.4558x; 1.1156x over previous
#include <cuda_runtime.h>
#include <cstdint>

#define EMBED   1024
#define HEADS   16
#define HDIM    64
#define BATCH   2
#define SEQ     2048
#define MTOT    (BATCH*SEQ)   // 4096

// Scratch (static __device__ -- no dynamic allocation allowed)
__device__ float g_qkv [(size_t)MTOT * 3 * EMBED];   // [4096, 3072]
__device__ float g_attn[(size_t)MTOT * EMBED];       // [4096, 1024]

// ============================================================================
// helpers
// ============================================================================
__device__ __forceinline__ uint32_t smem_u32(const void* p) {
    uint32_t a;
    asm("{ .reg .u64 t; cvta.to.shared.u64 t, %1; cvt.u32.u64 %0, t; }"
        : "=r"(a) : "l"(p));
    return a;
}
__device__ __forceinline__ float f2tf32(float x) {
    uint32_t u;
    asm("cvt.rna.tf32.f32 %0, %1;" : "=r"(u) : "f"(x));
    return __uint_as_float(u);
}
__device__ __forceinline__ void ldsm_x4(uint32_t* r, uint32_t addr) {
    asm volatile("ldmatrix.sync.aligned.m8n8.x4.shared.b16 {%0,%1,%2,%3}, [%4];"
        : "=r"(r[0]), "=r"(r[1]), "=r"(r[2]), "=r"(r[3]) : "r"(addr));
}
__device__ __forceinline__ void ldsm_x2(uint32_t* r, uint32_t addr) {
    asm volatile("ldmatrix.sync.aligned.m8n8.x2.shared.b16 {%0,%1}, [%2];"
        : "=r"(r[0]), "=r"(r[1]) : "r"(addr));
}
__device__ __forceinline__ void mma_tf32(float* d, const uint32_t* a, const uint32_t* b) {
    asm volatile(
        "mma.sync.aligned.m16n8k8.row.col.f32.tf32.tf32.f32 "
        "{%0,%1,%2,%3}, {%4,%5,%6,%7}, {%8,%9}, {%0,%1,%2,%3};"
        : "+f"(d[0]), "+f"(d[1]), "+f"(d[2]), "+f"(d[3])
        : "r"(a[0]), "r"(a[1]), "r"(a[2]), "r"(a[3]), "r"(b[0]), "r"(b[1]));
}

// ============================================================================
// tf32 tensor-core GEMM (NT): C[M,N] = A[M,K] @ B[N,K]^T + bias[N]
// CTA tile 128x128 (same as proven round-5), but 128 threads / 4 warps in
// 2x2 with 64x64 warp tiles: LDSM wavefronts per mma drop 1.5 -> 1.0
// (the measured L1 bottleneck), and 2 CTAs/SM become resident.
// ============================================================================
#define BKF 32
#define G_STAGE 32768            // A 16KB + B 16KB per stage
#define GEMM_DSMEM (2 * G_STAGE + 1024)

__global__ __launch_bounds__(128, 2)
void gemm_tf32_mma(const float* __restrict__ A,
                   const float* __restrict__ B,
                   const float* __restrict__ bias,
                   float* __restrict__ C,
                   int M, int N, int K)
{
    extern __shared__ char gsm[];
    const uint32_t raw  = smem_u32(gsm);
    const uint32_t base = (raw + 1023u) & ~1023u;
    char* pb = gsm + (base - raw);

    const int tid  = threadIdx.x;
    const int wid  = tid >> 5;          // 0..3
    const int lane = tid & 31;
    const int m0   = blockIdx.y * 128;
    const int n0   = blockIdx.x * 128;
    const int wm   = (wid & 1) * 64;    // warp m offset
    const int wn   = (wid >> 1) * 64;   // warp n offset

    // ---- loaders: one full 32-float row per thread, for both A and B
    const float* Arow = A + (size_t)(m0 + tid) * K;
    const float* Brow = B + (size_t)(n0 + tid) * K;
    uint32_t st_off[8];
#pragma unroll
    for (int q = 0; q < 8; q++) {
        uint32_t bo = (uint32_t)tid * 128u + q * 16u;
        st_off[q] = bo ^ ((bo >> 3) & 0x70);
    }

    // ---- ldmatrix addressing (identical lane patterns to proven version)
    const int aseg  = lane >> 3;
    const int arow  = wm + ((aseg & 1) << 3) + (lane & 7);
    const uint32_t akb = (uint32_t)((aseg >> 1) << 4);
    const int bseg  = (lane >> 3) & 1;
    const int brow  = wn + (lane & 7);
    const uint32_t bkb = (uint32_t)(bseg << 4);
    const uint32_t swmask = (uint32_t)((lane & 7) << 4);
    const uint32_t aRowByte = (uint32_t)arow * 128u;
    const uint32_t bRowByte = (uint32_t)brow * 128u;

    float acc[4][8][4];
#pragma unroll
    for (int i = 0; i < 4; i++)
#pragma unroll
        for (int j = 0; j < 8; j++)
#pragma unroll
            for (int r = 0; r < 4; r++) acc[i][j][r] = 0.f;

    const int KCH = K / BKF;
    float4 av[8], bv[8];

    // prologue: tile 0 -> stage 0
#pragma unroll
    for (int q = 0; q < 8; q++) {
        av[q] = *(const float4*)(Arow + q * 4);
        bv[q] = *(const float4*)(Brow + q * 4);
    }
#pragma unroll
    for (int q = 0; q < 8; q++) {
        float4 t;
        t.x = f2tf32(av[q].x); t.y = f2tf32(av[q].y);
        t.z = f2tf32(av[q].z); t.w = f2tf32(av[q].w);
        *(float4*)(pb + st_off[q]) = t;
        t.x = f2tf32(bv[q].x); t.y = f2tf32(bv[q].y);
        t.z = f2tf32(bv[q].z); t.w = f2tf32(bv[q].w);
        *(float4*)(pb + 16384 + st_off[q]) = t;
    }

    for (int kt = 0; kt < KCH; kt++) {
        __syncthreads();   // stage[kt&1] visible; stage[(kt+1)&1] free

        // issue global loads for kt+1 (latency hidden by the mma block)
        if (kt + 1 < KCH) {
            const float* a = Arow + (size_t)(kt + 1) * BKF;
            const float* b = Brow + (size_t)(kt + 1) * BKF;
#pragma unroll
            for (int q = 0; q < 8; q++) {
                av[q] = *(const float4*)(a + q * 4);
                bv[q] = *(const float4*)(b + q * 4);
            }
        }

        const uint32_t sAa = base + (uint32_t)(kt & 1) * G_STAGE;
        const uint32_t sBa = sAa + 16384u;
#pragma unroll
        for (int ks = 0; ks < 4; ks++) {
            const uint32_t kcolA = ((uint32_t)(ks * 32) + akb) ^ swmask;
            const uint32_t kcolB = ((uint32_t)(ks * 32) + bkb) ^ swmask;
            uint32_t afr[4][4], bfr[8][2];
#pragma unroll
            for (int mt = 0; mt < 4; mt++)
                ldsm_x4(afr[mt], sAa + aRowByte + (uint32_t)(mt * 16 * 128) + kcolA);
#pragma unroll
            for (int nt = 0; nt < 8; nt++)
                ldsm_x2(bfr[nt], sBa + bRowByte + (uint32_t)(nt * 8 * 128) + kcolB);
#pragma unroll
            for (int mt = 0; mt < 4; mt++)
#pragma unroll
                for (int nt = 0; nt < 8; nt++)
                    mma_tf32(acc[mt][nt], afr[mt], bfr[nt]);
        }

        // convert + store tile kt+1 into the other stage
        if (kt + 1 < KCH) {
            char* dst = pb + ((kt + 1) & 1) * G_STAGE;
#pragma unroll
            for (int q = 0; q < 8; q++) {
                float4 t;
                t.x = f2tf32(av[q].x); t.y = f2tf32(av[q].y);
                t.z = f2tf32(av[q].z); t.w = f2tf32(av[q].w);
                *(float4*)(dst + st_off[q]) = t;
                t.x = f2tf32(bv[q].x); t.y = f2tf32(bv[q].y);
                t.z = f2tf32(bv[q].z); t.w = f2tf32(bv[q].w);
                *(float4*)(dst + 16384 + st_off[q]) = t;
            }
        }
    }

    const int rbase = m0 + wm + (lane >> 2);
    const int cbase = n0 + wn + (lane & 3) * 2;
#pragma unroll
    for (int mt = 0; mt < 4; mt++) {
        const int r0 = rbase + mt * 16;
#pragma unroll
        for (int nt = 0; nt < 8; nt++) {
            const int c = cbase + nt * 8;
            const float b0 = __ldg(bias + c);
            const float b1 = __ldg(bias + c + 1);
            float2 v0, v1;
            v0.x = acc[mt][nt][0] + b0; v0.y = acc[mt][nt][1] + b1;
            v1.x = acc[mt][nt][2] + b0; v1.y = acc[mt][nt][3] + b1;
            *(float2*)&C[(size_t)r0 * N + c]       = v0;
            *(float2*)&C[(size_t)(r0 + 8) * N + c] = v1;
        }
    }
}

// ============================================================================
// Tensor-core flash attention (tf32 mma) — ROUND-4 EXACT (best measured):
// BQ=128, 256 threads / 8 warps, 16 q-rows/warp, direct LDG, x2 B-frags.
// ============================================================================
#define BQ  128
#define BKV 64

// smem layout (bytes from 1024-aligned base):
//  sQ  [128][64]f : 0      .. 32768
//  sK  [ 64][64]f : 32768  .. 49152
//  sVT [ 64][64]f : 49152  .. 65536
//  sP  [128][64]f : 65536  .. 98304
//  sM  [64]i      : 98304  .. 98560
#define FA_SMEM (98560 + 1024)

__device__ __forceinline__ uint32_t sw256(int row, int chunk) {
    return (uint32_t)row * 256u + (uint32_t)((chunk ^ (row & 7)) << 4);
}

__global__ __launch_bounds__(256, 1)
void flash_attn_tc(const float* __restrict__ qkv,
                   const int*   __restrict__ mask,
                   float*       __restrict__ out)
{
    extern __shared__ char fsm[];
    const uint32_t raw  = smem_u32(fsm);
    const uint32_t base = (raw + 1023u) & ~1023u;
    char* pb = fsm + (base - raw);
    char* sQ  = pb;
    char* sK  = pb + 32768;
    char* sVT = pb + 49152;
    char* sP  = pb + 65536;
    int*  sM  = (int*)(pb + 98304);
    const uint32_t aQ  = base;
    const uint32_t aK  = base + 32768;
    const uint32_t aVT = base + 49152;
    const uint32_t aP  = base + 65536;

    const int tid  = threadIdx.x;
    const int wid  = tid >> 5;
    const int lane = tid & 31;
    const int qb   = blockIdx.x;
    const int h    = blockIdx.y;
    const int b    = blockIdx.z;

    const size_t rs = 3 * EMBED;
    const float* qg = qkv + (size_t)(b * SEQ) * rs + h * HDIM;
    const float* kg = qg + EMBED;
    const float* vg = qg + 2 * EMBED;
    const int*   mg = mask + b * SEQ;

    // ---- load Q tile [128][64]
    {
        const int r  = tid >> 1;
        const int cb = (tid & 1) * 8;
        const float* src = qg + (size_t)(qb * BQ + r) * rs;
#pragma unroll
        for (int q = 0; q < 8; q++) {
            const int c = cb + q;
            float4 v = *(const float4*)(src + c * 4);
            v.x = f2tf32(v.x); v.y = f2tf32(v.y);
            v.z = f2tf32(v.z); v.w = f2tf32(v.w);
            *(float4*)(sQ + sw256(r, c)) = v;
        }
    }
    __syncthreads();

    // ---- hoist Q fragments for all 8 k-steps
    const int arow = wid * 16 + ((lane >> 3) & 1) * 8 + (lane & 7);
    const int ach  = lane >> 4;
    uint32_t qf[8][4];
#pragma unroll
    for (int ks = 0; ks < 8; ks++)
        ldsm_x4(qf[ks], aQ + sw256(arow, ks * 2 + ach));

    const int bln = lane & 7;
    const int bch = (lane >> 3) & 1;

    float m_i[2] = {-1e30f, -1e30f};
    float l_i[2] = {0.f, 0.f};
    float oacc[8][4];
#pragma unroll
    for (int j = 0; j < 8; j++)
#pragma unroll
        for (int r = 0; r < 4; r++) oacc[j][r] = 0.f;

    for (int kt = 0; kt < SEQ / BKV; kt++) {
        __syncthreads();   // prev PV mma done reading sK/sVT/sP

        // ---- load K tile [64 keys][64 d]
        {
            const int r  = tid >> 2;
            const int cb = (tid & 3) * 4;
            const float* src = kg + (size_t)(kt * BKV + r) * rs;
#pragma unroll
            for (int q = 0; q < 4; q++) {
                const int c = cb + q;
                float4 v = *(const float4*)(src + c * 4);
                v.x = f2tf32(v.x); v.y = f2tf32(v.y);
                v.z = f2tf32(v.z); v.w = f2tf32(v.w);
                *(float4*)(sK + sw256(r, c)) = v;
            }
        }
        // ---- load V tile transposed -> sVT[d][key]
        {
            const int key = tid >> 2;
            const int db  = (tid & 3) * 16;
            const float* src = vg + (size_t)(kt * BKV + key) * rs + db;
            const int kc = key >> 2;
            const int kb = (key & 3) * 4;
#pragma unroll
            for (int q = 0; q < 4; q++) {
                float4 v = *(const float4*)(src + q * 4);
                const int d0 = db + q * 4;
                *(float*)(sVT + sw256(d0 + 0, kc) + kb) = f2tf32(v.x);
                *(float*)(sVT + sw256(d0 + 1, kc) + kb) = f2tf32(v.y);
                *(float*)(sVT + sw256(d0 + 2, kc) + kb) = f2tf32(v.z);
                *(float*)(sVT + sw256(d0 + 3, kc) + kb) = f2tf32(v.w);
            }
        }
        if (tid < BKV) sM[tid] = mg[kt * BKV + tid];
        __syncthreads();

        // ---- S = Q K^T : per warp 16 x 64
        float sacc[8][4];
#pragma unroll
        for (int j = 0; j < 8; j++)
#pragma unroll
            for (int r = 0; r < 4; r++) sacc[j][r] = 0.f;
#pragma unroll
        for (int ks = 0; ks < 8; ks++) {
            uint32_t bfr[8][2];
#pragma unroll
            for (int nf = 0; nf < 8; nf++)
                ldsm_x2(bfr[nf], aK + sw256(nf * 8 + bln, ks * 2 + bch));
#pragma unroll
            for (int nf = 0; nf < 8; nf++)
                mma_tf32(sacc[nf], qf[ks], bfr[nf]);
        }

        // ---- fragment softmax
        float rmax0 = -1e30f, rmax1 = -1e30f;
#pragma unroll
        for (int j = 0; j < 8; j++) {
            const int c = j * 8 + (lane & 3) * 2;
            const int mk0 = sM[c], mk1 = sM[c + 1];
            sacc[j][0] = mk0 ? sacc[j][0] * 0.125f : -1e30f;
            sacc[j][1] = mk1 ? sacc[j][1] * 0.125f : -1e30f;
            sacc[j][2] = mk0 ? sacc[j][2] * 0.125f : -1e30f;
            sacc[j][3] = mk1 ? sacc[j][3] * 0.125f : -1e30f;
            rmax0 = fmaxf(rmax0, fmaxf(sacc[j][0], sacc[j][1]));
            rmax1 = fmaxf(rmax1, fmaxf(sacc[j][2], sacc[j][3]));
        }
        rmax0 = fmaxf(rmax0, __shfl_xor_sync(0xffffffffu, rmax0, 1));
        rmax0 = fmaxf(rmax0, __shfl_xor_sync(0xffffffffu, rmax0, 2));
        rmax1 = fmaxf(rmax1, __shfl_xor_sync(0xffffffffu, rmax1, 1));
        rmax1 = fmaxf(rmax1, __shfl_xor_sync(0xffffffffu, rmax1, 2));

        const float mn0 = fmaxf(m_i[0], rmax0);
        const float mn1 = fmaxf(m_i[1], rmax1);
        const float cr0 = __expf(m_i[0] - mn0);
        const float cr1 = __expf(m_i[1] - mn1);
        m_i[0] = mn0; m_i[1] = mn1;

        float rsum0 = 0.f, rsum1 = 0.f;
#pragma unroll
        for (int j = 0; j < 8; j++) {
            sacc[j][0] = __expf(sacc[j][0] - mn0);
            sacc[j][1] = __expf(sacc[j][1] - mn0);
            sacc[j][2] = __expf(sacc[j][2] - mn1);
            sacc[j][3] = __expf(sacc[j][3] - mn1);
            rsum0 += sacc[j][0] + sacc[j][1];
            rsum1 += sacc[j][2] + sacc[j][3];
        }
        rsum0 += __shfl_xor_sync(0xffffffffu, rsum0, 1);
        rsum0 += __shfl_xor_sync(0xffffffffu, rsum0, 2);
        rsum1 += __shfl_xor_sync(0xffffffffu, rsum1, 1);
        rsum1 += __shfl_xor_sync(0xffffffffu, rsum1, 2);
        l_i[0] = l_i[0] * cr0 + rsum0;
        l_i[1] = l_i[1] * cr1 + rsum1;

#pragma unroll
        for (int j = 0; j < 8; j++) {
            oacc[j][0] *= cr0; oacc[j][1] *= cr0;
            oacc[j][2] *= cr1; oacc[j][3] *= cr1;
        }

        // ---- store P (tf32); rows warp-local
        {
            const int r0 = wid * 16 + (lane >> 2);
#pragma unroll
            for (int j = 0; j < 8; j++) {
                const int c = j * 8 + (lane & 3) * 2;
                const int ch = c >> 2;
                const int cb = (c & 3) * 4;
                float2 v0, v1;
                v0.x = f2tf32(sacc[j][0]); v0.y = f2tf32(sacc[j][1]);
                v1.x = f2tf32(sacc[j][2]); v1.y = f2tf32(sacc[j][3]);
                *(float2*)(sP + sw256(r0,     ch) + cb) = v0;
                *(float2*)(sP + sw256(r0 + 8, ch) + cb) = v1;
            }
        }
        __syncwarp();

        // ---- O += P V^T
#pragma unroll
        for (int ks = 0; ks < 8; ks++) {
            uint32_t af[4];
            ldsm_x4(af, aP + sw256(arow, ks * 2 + ach));
            uint32_t bfr[8][2];
#pragma unroll
            for (int nf = 0; nf < 8; nf++)
                ldsm_x2(bfr[nf], aVT + sw256(nf * 8 + bln, ks * 2 + bch));
#pragma unroll
            for (int nf = 0; nf < 8; nf++)
                mma_tf32(oacc[nf], af, bfr[nf]);
        }
    }

    // ---- epilogue: normalize, write to [b, s, h*64 + d]
    const float inv0 = 1.0f / l_i[0];
    const float inv1 = 1.0f / l_i[1];
    const int r0 = qb * BQ + wid * 16 + (lane >> 2);
    const int c0 = h * HDIM + (lane & 3) * 2;
#pragma unroll
    for (int j = 0; j < 8; j++) {
        const int c = c0 + j * 8;
        float2 v0, v1;
        v0.x = oacc[j][0] * inv0; v0.y = oacc[j][1] * inv0;
        v1.x = oacc[j][2] * inv1; v1.y = oacc[j][3] * inv1;
        *(float2*)&out[(size_t)(b * SEQ + r0)     * EMBED + c] = v0;
        *(float2*)&out[(size_t)(b * SEQ + r0 + 8) * EMBED + c] = v1;
    }
}

// ---------------------------------------------------------------------------
extern "C" void kernel_launch(void* const* d_in, const int* in_sizes, int n_in,
                              void* d_out, int out_size)
{
    const float* x    = (const float*)d_in[0];
    const int*   mask = (const int*)  d_in[1];
    const float* Wqkv = (const float*)d_in[2];
    const float* bqkv = (const float*)d_in[3];
    const float* Wout = (const float*)d_in[4];
    const float* bout = (const float*)d_in[5];
    float* out = (float*)d_out;

    float *qkv = nullptr, *attn = nullptr;
    cudaGetSymbolAddress((void**)&qkv,  g_qkv);
    cudaGetSymbolAddress((void**)&attn, g_attn);

    cudaFuncSetAttribute(gemm_tf32_mma,
                         cudaFuncAttributeMaxDynamicSharedMemorySize, GEMM_DSMEM);
    cudaFuncSetAttribute(flash_attn_tc,
                         cudaFuncAttributeMaxDynamicSharedMemorySize, FA_SMEM);

    // 1) qkv = x @ Wqkv^T + bqkv       [4096, 3072]
    {
        dim3 grid((3 * EMBED) / 128, MTOT / 128);
        gemm_tf32_mma<<<grid, 128, GEMM_DSMEM>>>(x, Wqkv, bqkv, qkv,
                                                 MTOT, 3 * EMBED, EMBED);
    }
    // 2) flash attention -> attn       [4096, 1024]
    {
        dim3 grid(SEQ / BQ, HEADS, BATCH);
        flash_attn_tc<<<grid, 256, FA_SMEM>>>(qkv, mask, attn);
    }
    // 3) out = attn @ Wout^T + bout    [4096, 1024]
    {
        dim3 grid(EMBED / 128, MTOT / 128);
        gemm_tf32_mma<<<grid, 128, GEMM_DSMEM>>>(attn, Wout, bout, out,
                                                 MTOT, EMBED, EMBED);
    }
}

// round 12
// speedup vs baseline: 1.8113x; 1.2442x over previous
#include <cuda_runtime.h>
#include <cstdint>

#define EMBED   1024
#define HEADS   16
#define HDIM    64
#define BATCH   2
#define SEQ     2048
#define MTOT    (BATCH*SEQ)   // 4096

// Scratch (static __device__ -- no dynamic allocation allowed)
__device__ float g_qkv [(size_t)MTOT * 3 * EMBED];   // [4096, 3072]
__device__ float g_attn[(size_t)MTOT * EMBED];       // [4096, 1024]

// ============================================================================
// helpers
// ============================================================================
__device__ __forceinline__ uint32_t smem_u32(const void* p) {
    uint32_t a;
    asm("{ .reg .u64 t; cvta.to.shared.u64 t, %1; cvt.u32.u64 %0, t; }"
        : "=r"(a) : "l"(p));
    return a;
}
__device__ __forceinline__ float f2tf32(float x) {
    uint32_t u;
    asm("cvt.rna.tf32.f32 %0, %1;" : "=r"(u) : "f"(x));
    return __uint_as_float(u);
}
__device__ __forceinline__ void ldsm_x4(uint32_t* r, uint32_t addr) {
    asm volatile("ldmatrix.sync.aligned.m8n8.x4.shared.b16 {%0,%1,%2,%3}, [%4];"
        : "=r"(r[0]), "=r"(r[1]), "=r"(r[2]), "=r"(r[3]) : "r"(addr));
}
__device__ __forceinline__ void ldsm_x2(uint32_t* r, uint32_t addr) {
    asm volatile("ldmatrix.sync.aligned.m8n8.x2.shared.b16 {%0,%1}, [%2];"
        : "=r"(r[0]), "=r"(r[1]) : "r"(addr));
}
__device__ __forceinline__ void mma_tf32(float* d, const uint32_t* a, const uint32_t* b) {
    asm volatile(
        "mma.sync.aligned.m16n8k8.row.col.f32.tf32.tf32.f32 "
        "{%0,%1,%2,%3}, {%4,%5,%6,%7}, {%8,%9}, {%0,%1,%2,%3};"
        : "+f"(d[0]), "+f"(d[1]), "+f"(d[2]), "+f"(d[3])
        : "r"(a[0]), "r"(a[1]), "r"(a[2]), "r"(a[3]), "r"(b[0]), "r"(b[1]));
}

// ============================================================================
// tf32 tensor-core GEMM (NT): C[M,N] = A[M,K] @ B[N,K]^T + bias[N]
// ROUND-5 EXACT (best proven GEMM): 256 thr, 2x4 warps, 64x32 warp tile,
// 2-stage smem pipeline, x2 B-fragment loads.
// ============================================================================
#define BKF 32
#define G_STAGE 32768
#define GEMM_DSMEM (2 * G_STAGE + 1024)

__global__ __launch_bounds__(256, 1)
void gemm_tf32_mma(const float* __restrict__ A,
                   const float* __restrict__ B,
                   const float* __restrict__ bias,
                   float* __restrict__ C,
                   int M, int N, int K)
{
    extern __shared__ char gsm[];
    const uint32_t raw  = smem_u32(gsm);
    const uint32_t base = (raw + 1023u) & ~1023u;
    char* pb = gsm + (base - raw);

    const int tid  = threadIdx.x;
    const int wid  = tid >> 5;
    const int lane = tid & 31;
    const int m0   = blockIdx.y * 128;
    const int n0   = blockIdx.x * 128;
    const int wm   = (wid & 1) * 64;
    const int wn   = (wid >> 1) * 32;

    const int lrow  = tid >> 1;
    const int lhalf = tid & 1;
    const float* Arow = A + (size_t)(m0 + lrow) * K + lhalf * 16;
    const float* Brow = B + (size_t)(n0 + lrow) * K + lhalf * 16;
    uint32_t st_off[4];
#pragma unroll
    for (int q = 0; q < 4; q++) {
        uint32_t bo = (uint32_t)lrow * 128u + (uint32_t)lhalf * 64u + q * 16u;
        st_off[q] = bo ^ ((bo >> 3) & 0x70);
    }

    const int aseg  = lane >> 3;
    const int arow  = wm + ((aseg & 1) << 3) + (lane & 7);
    const uint32_t akb = (uint32_t)((aseg >> 1) << 4);
    const int bseg  = (lane >> 3) & 1;
    const int brow  = wn + (lane & 7);
    const uint32_t bkb = (uint32_t)(bseg << 4);
    const uint32_t swmask = (uint32_t)((lane & 7) << 4);
    const uint32_t aRowByte = (uint32_t)arow * 128u;
    const uint32_t bRowByte = (uint32_t)brow * 128u;

    float acc[4][4][4];
#pragma unroll
    for (int i = 0; i < 4; i++)
#pragma unroll
        for (int j = 0; j < 4; j++)
#pragma unroll
            for (int r = 0; r < 4; r++) acc[i][j][r] = 0.f;

    const int KCH = K / BKF;
    float4 av[4], bv[4];

#pragma unroll
    for (int q = 0; q < 4; q++) {
        av[q] = *(const float4*)(Arow + q * 4);
        bv[q] = *(const float4*)(Brow + q * 4);
    }
#pragma unroll
    for (int q = 0; q < 4; q++) {
        float4 t;
        t.x = f2tf32(av[q].x); t.y = f2tf32(av[q].y);
        t.z = f2tf32(av[q].z); t.w = f2tf32(av[q].w);
        *(float4*)(pb + st_off[q]) = t;
        t.x = f2tf32(bv[q].x); t.y = f2tf32(bv[q].y);
        t.z = f2tf32(bv[q].z); t.w = f2tf32(bv[q].w);
        *(float4*)(pb + 16384 + st_off[q]) = t;
    }

    for (int kt = 0; kt < KCH; kt++) {
        __syncthreads();

        if (kt + 1 < KCH) {
            const float* a = Arow + (size_t)(kt + 1) * BKF;
            const float* b = Brow + (size_t)(kt + 1) * BKF;
#pragma unroll
            for (int q = 0; q < 4; q++) {
                av[q] = *(const float4*)(a + q * 4);
                bv[q] = *(const float4*)(b + q * 4);
            }
        }

        const uint32_t sAa = base + (uint32_t)(kt & 1) * G_STAGE;
        const uint32_t sBa = sAa + 16384u;
#pragma unroll
        for (int ks = 0; ks < 4; ks++) {
            const uint32_t kcolA = ((uint32_t)(ks * 32) + akb) ^ swmask;
            const uint32_t kcolB = ((uint32_t)(ks * 32) + bkb) ^ swmask;
            uint32_t afr[4][4], bfr[4][2];
#pragma unroll
            for (int mt = 0; mt < 4; mt++)
                ldsm_x4(afr[mt], sAa + aRowByte + (uint32_t)(mt * 16 * 128) + kcolA);
#pragma unroll
            for (int nt = 0; nt < 4; nt++)
                ldsm_x2(bfr[nt], sBa + bRowByte + (uint32_t)(nt * 8 * 128) + kcolB);
#pragma unroll
            for (int mt = 0; mt < 4; mt++)
#pragma unroll
                for (int nt = 0; nt < 4; nt++)
                    mma_tf32(acc[mt][nt], afr[mt], bfr[nt]);
        }

        if (kt + 1 < KCH) {
            char* dst = pb + ((kt + 1) & 1) * G_STAGE;
#pragma unroll
            for (int q = 0; q < 4; q++) {
                float4 t;
                t.x = f2tf32(av[q].x); t.y = f2tf32(av[q].y);
                t.z = f2tf32(av[q].z); t.w = f2tf32(av[q].w);
                *(float4*)(dst + st_off[q]) = t;
                t.x = f2tf32(bv[q].x); t.y = f2tf32(bv[q].y);
                t.z = f2tf32(bv[q].z); t.w = f2tf32(bv[q].w);
                *(float4*)(dst + 16384 + st_off[q]) = t;
            }
        }
    }

    const int rbase = m0 + wm + (lane >> 2);
    const int cbase = n0 + wn + (lane & 3) * 2;
#pragma unroll
    for (int mt = 0; mt < 4; mt++) {
        const int r0 = rbase + mt * 16;
#pragma unroll
        for (int nt = 0; nt < 4; nt++) {
            const int c = cbase + nt * 8;
            const float b0 = __ldg(bias + c);
            const float b1 = __ldg(bias + c + 1);
            float2 v0, v1;
            v0.x = acc[mt][nt][0] + b0; v0.y = acc[mt][nt][1] + b1;
            v1.x = acc[mt][nt][2] + b0; v1.y = acc[mt][nt][3] + b1;
            *(float2*)&C[(size_t)r0 * N + c]       = v0;
            *(float2*)&C[(size_t)(r0 + 8) * N + c] = v1;
        }
    }
}

// ============================================================================
// Tensor-core flash attention (tf32 mma), BQ=256.
// 256 threads / 8 warps; each warp owns 32 q-rows (2 m-tiles, processed
// sequentially through softmax so only one sacc is live). K/V staging work
// amortizes over 2x q-rows; PV B-fragments shared across both m-tiles.
// ============================================================================
#define BQ  256
#define BKV 64

// smem layout (bytes from 1024-aligned base):
//  sQ  [256][64]f : 0       .. 65536
//  sK  [ 64][64]f : 65536   .. 81920
//  sVT [ 64][64]f : 81920   .. 98304
//  sP  [256][64]f : 98304   .. 163840
//  sM  [64]i      : 163840  .. 164096
#define FA_SMEM (164096 + 1024)

__device__ __forceinline__ uint32_t sw256(int row, int chunk) {
    return (uint32_t)row * 256u + (uint32_t)((chunk ^ (row & 7)) << 4);
}

__global__ __launch_bounds__(256, 1)
void flash_attn_tc(const float* __restrict__ qkv,
                   const int*   __restrict__ mask,
                   float*       __restrict__ out)
{
    extern __shared__ char fsm[];
    const uint32_t raw  = smem_u32(fsm);
    const uint32_t base = (raw + 1023u) & ~1023u;
    char* pb = fsm + (base - raw);
    char* sQ  = pb;
    char* sK  = pb + 65536;
    char* sVT = pb + 81920;
    char* sP  = pb + 98304;
    int*  sM  = (int*)(pb + 163840);
    const uint32_t aQ  = base;
    const uint32_t aK  = base + 65536;
    const uint32_t aVT = base + 81920;
    const uint32_t aP  = base + 98304;

    const int tid  = threadIdx.x;
    const int wid  = tid >> 5;
    const int lane = tid & 31;
    const int qb   = blockIdx.x;     // 0..7
    const int h    = blockIdx.y;
    const int b    = blockIdx.z;

    const size_t rs = 3 * EMBED;
    const float* qg = qkv + (size_t)(b * SEQ) * rs + h * HDIM;
    const float* kg = qg + EMBED;
    const float* vg = qg + 2 * EMBED;
    const int*   mg = mask + b * SEQ;

    // ---- load Q tile [256][64]: one row per thread, 16 chunks
    {
        const float* src = qg + (size_t)(qb * BQ + tid) * rs;
#pragma unroll
        for (int c = 0; c < 16; c++) {
            float4 v = *(const float4*)(src + c * 4);
            v.x = f2tf32(v.x); v.y = f2tf32(v.y);
            v.z = f2tf32(v.z); v.w = f2tf32(v.w);
            *(float4*)(sQ + sw256(tid, c)) = v;
        }
    }
    __syncthreads();

    // ---- hoist Q fragments: 2 m-tiles x 8 k-steps
    const int arow0 = wid * 32 + ((lane >> 3) & 1) * 8 + (lane & 7);
    const int ach   = lane >> 4;
    uint32_t qf[2][8][4];
#pragma unroll
    for (int mt = 0; mt < 2; mt++)
#pragma unroll
        for (int ks = 0; ks < 8; ks++)
            ldsm_x4(qf[mt][ks], aQ + sw256(arow0 + mt * 16, ks * 2 + ach));

    const int bln = lane & 7;
    const int bch = (lane >> 3) & 1;

    float m_i[2][2], l_i[2][2];
#pragma unroll
    for (int mt = 0; mt < 2; mt++) {
        m_i[mt][0] = -1e30f; m_i[mt][1] = -1e30f;
        l_i[mt][0] = 0.f;    l_i[mt][1] = 0.f;
    }
    float oacc[2][8][4];
#pragma unroll
    for (int mt = 0; mt < 2; mt++)
#pragma unroll
        for (int j = 0; j < 8; j++)
#pragma unroll
            for (int r = 0; r < 4; r++) oacc[mt][j][r] = 0.f;

    for (int kt = 0; kt < SEQ / BKV; kt++) {
        __syncthreads();   // prev PV mma done reading sK/sVT/sP

        // ---- load K tile [64 keys][64 d]: row = tid>>2, 4 chunks
        {
            const int r  = tid >> 2;
            const int cb = (tid & 3) * 4;
            const float* src = kg + (size_t)(kt * BKV + r) * rs;
#pragma unroll
            for (int q = 0; q < 4; q++) {
                const int c = cb + q;
                float4 v = *(const float4*)(src + c * 4);
                v.x = f2tf32(v.x); v.y = f2tf32(v.y);
                v.z = f2tf32(v.z); v.w = f2tf32(v.w);
                *(float4*)(sK + sw256(r, c)) = v;
            }
        }
        // ---- load V tile transposed -> sVT[d][key]
        {
            const int key = tid >> 2;
            const int db  = (tid & 3) * 16;
            const float* src = vg + (size_t)(kt * BKV + key) * rs + db;
            const int kc = key >> 2;
            const int kb = (key & 3) * 4;
#pragma unroll
            for (int q = 0; q < 4; q++) {
                float4 v = *(const float4*)(src + q * 4);
                const int d0 = db + q * 4;
                *(float*)(sVT + sw256(d0 + 0, kc) + kb) = f2tf32(v.x);
                *(float*)(sVT + sw256(d0 + 1, kc) + kb) = f2tf32(v.y);
                *(float*)(sVT + sw256(d0 + 2, kc) + kb) = f2tf32(v.z);
                *(float*)(sVT + sw256(d0 + 3, kc) + kb) = f2tf32(v.w);
            }
        }
        if (tid < BKV) sM[tid] = mg[kt * BKV + tid];
        __syncthreads();

        // ---- per m-tile: S = Q K^T, softmax, P store (sequential: one sacc live)
#pragma unroll
        for (int mt = 0; mt < 2; mt++) {
            float sacc[8][4];
#pragma unroll
            for (int j = 0; j < 8; j++)
#pragma unroll
                for (int r = 0; r < 4; r++) sacc[j][r] = 0.f;
#pragma unroll
            for (int ks = 0; ks < 8; ks++) {
                uint32_t bfr[8][2];
#pragma unroll
                for (int nf = 0; nf < 8; nf++)
                    ldsm_x2(bfr[nf], aK + sw256(nf * 8 + bln, ks * 2 + bch));
#pragma unroll
                for (int nf = 0; nf < 8; nf++)
                    mma_tf32(sacc[nf], qf[mt][ks], bfr[nf]);
            }

            float rmax0 = -1e30f, rmax1 = -1e30f;
#pragma unroll
            for (int j = 0; j < 8; j++) {
                const int c = j * 8 + (lane & 3) * 2;
                const int mk0 = sM[c], mk1 = sM[c + 1];
                sacc[j][0] = mk0 ? sacc[j][0] * 0.125f : -1e30f;
                sacc[j][1] = mk1 ? sacc[j][1] * 0.125f : -1e30f;
                sacc[j][2] = mk0 ? sacc[j][2] * 0.125f : -1e30f;
                sacc[j][3] = mk1 ? sacc[j][3] * 0.125f : -1e30f;
                rmax0 = fmaxf(rmax0, fmaxf(sacc[j][0], sacc[j][1]));
                rmax1 = fmaxf(rmax1, fmaxf(sacc[j][2], sacc[j][3]));
            }
            rmax0 = fmaxf(rmax0, __shfl_xor_sync(0xffffffffu, rmax0, 1));
            rmax0 = fmaxf(rmax0, __shfl_xor_sync(0xffffffffu, rmax0, 2));
            rmax1 = fmaxf(rmax1, __shfl_xor_sync(0xffffffffu, rmax1, 1));
            rmax1 = fmaxf(rmax1, __shfl_xor_sync(0xffffffffu, rmax1, 2));

            const float mn0 = fmaxf(m_i[mt][0], rmax0);
            const float mn1 = fmaxf(m_i[mt][1], rmax1);
            const float cr0 = __expf(m_i[mt][0] - mn0);
            const float cr1 = __expf(m_i[mt][1] - mn1);
            m_i[mt][0] = mn0; m_i[mt][1] = mn1;

            float rsum0 = 0.f, rsum1 = 0.f;
#pragma unroll
            for (int j = 0; j < 8; j++) {
                sacc[j][0] = __expf(sacc[j][0] - mn0);
                sacc[j][1] = __expf(sacc[j][1] - mn0);
                sacc[j][2] = __expf(sacc[j][2] - mn1);
                sacc[j][3] = __expf(sacc[j][3] - mn1);
                rsum0 += sacc[j][0] + sacc[j][1];
                rsum1 += sacc[j][2] + sacc[j][3];
            }
            rsum0 += __shfl_xor_sync(0xffffffffu, rsum0, 1);
            rsum0 += __shfl_xor_sync(0xffffffffu, rsum0, 2);
            rsum1 += __shfl_xor_sync(0xffffffffu, rsum1, 1);
            rsum1 += __shfl_xor_sync(0xffffffffu, rsum1, 2);
            l_i[mt][0] = l_i[mt][0] * cr0 + rsum0;
            l_i[mt][1] = l_i[mt][1] * cr1 + rsum1;

#pragma unroll
            for (int j = 0; j < 8; j++) {
                oacc[mt][j][0] *= cr0; oacc[mt][j][1] *= cr0;
                oacc[mt][j][2] *= cr1; oacc[mt][j][3] *= cr1;
            }

            const int r0 = wid * 32 + mt * 16 + (lane >> 2);
#pragma unroll
            for (int j = 0; j < 8; j++) {
                const int c = j * 8 + (lane & 3) * 2;
                const int ch = c >> 2;
                const int cb = (c & 3) * 4;
                float2 v0, v1;
                v0.x = f2tf32(sacc[j][0]); v0.y = f2tf32(sacc[j][1]);
                v1.x = f2tf32(sacc[j][2]); v1.y = f2tf32(sacc[j][3]);
                *(float2*)(sP + sw256(r0,     ch) + cb) = v0;
                *(float2*)(sP + sw256(r0 + 8, ch) + cb) = v1;
            }
        }
        __syncwarp();

        // ---- O += P V^T : B-fragments loaded ONCE per ks, shared by both mt
#pragma unroll
        for (int ks = 0; ks < 8; ks++) {
            uint32_t af[2][4];
#pragma unroll
            for (int mt = 0; mt < 2; mt++)
                ldsm_x4(af[mt], aP + sw256(arow0 + mt * 16, ks * 2 + ach));
            uint32_t bfr[8][2];
#pragma unroll
            for (int nf = 0; nf < 8; nf++)
                ldsm_x2(bfr[nf], aVT + sw256(nf * 8 + bln, ks * 2 + bch));
#pragma unroll
            for (int mt = 0; mt < 2; mt++)
#pragma unroll
                for (int nf = 0; nf < 8; nf++)
                    mma_tf32(oacc[mt][nf], af[mt], bfr[nf]);
        }
    }

    // ---- epilogue: normalize, write to [b, s, h*64 + d]
#pragma unroll
    for (int mt = 0; mt < 2; mt++) {
        const float inv0 = 1.0f / l_i[mt][0];
        const float inv1 = 1.0f / l_i[mt][1];
        const int r0 = qb * BQ + wid * 32 + mt * 16 + (lane >> 2);
        const int c0 = h * HDIM + (lane & 3) * 2;
#pragma unroll
        for (int j = 0; j < 8; j++) {
            const int c = c0 + j * 8;
            float2 v0, v1;
            v0.x = oacc[mt][j][0] * inv0; v0.y = oacc[mt][j][1] * inv0;
            v1.x = oacc[mt][j][2] * inv1; v1.y = oacc[mt][j][3] * inv1;
            *(float2*)&out[(size_t)(b * SEQ + r0)     * EMBED + c] = v0;
            *(float2*)&out[(size_t)(b * SEQ + r0 + 8) * EMBED + c] = v1;
        }
    }
}

// ---------------------------------------------------------------------------
extern "C" void kernel_launch(void* const* d_in, const int* in_sizes, int n_in,
                              void* d_out, int out_size)
{
    const float* x    = (const float*)d_in[0];
    const int*   mask = (const int*)  d_in[1];
    const float* Wqkv = (const float*)d_in[2];
    const float* bqkv = (const float*)d_in[3];
    const float* Wout = (const float*)d_in[4];
    const float* bout = (const float*)d_in[5];
    float* out = (float*)d_out;

    float *qkv = nullptr, *attn = nullptr;
    cudaGetSymbolAddress((void**)&qkv,  g_qkv);
    cudaGetSymbolAddress((void**)&attn, g_attn);

    cudaFuncSetAttribute(gemm_tf32_mma,
                         cudaFuncAttributeMaxDynamicSharedMemorySize, GEMM_DSMEM);
    cudaFuncSetAttribute(flash_attn_tc,
                         cudaFuncAttributeMaxDynamicSharedMemorySize, FA_SMEM);

    // 1) qkv = x @ Wqkv^T + bqkv       [4096, 3072]
    {
        dim3 grid((3 * EMBED) / 128, MTOT / 128);
        gemm_tf32_mma<<<grid, 256, GEMM_DSMEM>>>(x, Wqkv, bqkv, qkv,
                                                 MTOT, 3 * EMBED, EMBED);
    }
    // 2) flash attention -> attn       [4096, 1024]
    {
        dim3 grid(SEQ / BQ, HEADS, BATCH);
        flash_attn_tc<<<grid, 256, FA_SMEM>>>(qkv, mask, attn);
    }
    // 3) out = attn @ Wout^T + bout    [4096, 1024]
    {
        dim3 grid(EMBED / 128, MTOT / 128);
        gemm_tf32_mma<<<grid, 256, GEMM_DSMEM>>>(attn, Wout, bout, out,
                                                 MTOT, EMBED, EMBED);
    }
}